// round 16
// baseline (speedup 1.0000x reference)
#include <cuda_runtime.h>
#include <cuda_fp16.h>
#include <cstdint>

// ---------------------------------------------------------------------------
// SimCLR (NT-Xent) loss, B=4096, D=128, T=0.1 — symmetric triangular GEMM.
// f16 HMMA, 3 CTAs/SM, A cached per chunk, B streamed at SLAB (16KB)
// granularity so copies overlap the opposite half of the mainloop + epilogue.
// ---------------------------------------------------------------------------

#define BROWS    4096
#define TWOB     8192
#define DDIM     128
#define NTILES   64
#define NBLOCKS  (NTILES * (NTILES + 1) / 2)   // 2080
#define TILE_BYTES 32768
#define SLAB_BYTES 16384
#define GRID_GEMM  444                         // 3 per SM
#define EXP_SCALE 14.4269504089f               // 10 * log2(e)

__device__ __half        g_zh[TWOB * DDIM];    // f16, tile-local SW128 layout
__device__ float         g_zf[TWOB * DDIM];    // row-major fp32 (positives)
__device__ float         g_partial[TWOB * NTILES];  // [row][tile]
__device__ float         g_ploss[64];
__device__ float         g_possum[64];
__device__ int           g_ctr = 0;

// ---------------------------------------------------------------------------
__device__ __forceinline__ float ex2f(float x) {
    float y;
    asm("ex2.approx.ftz.f32 %0, %1;" : "=f"(y) : "f"(x));
    return y;
}

__device__ __forceinline__ void mma16816h(uint32_t& d0, uint32_t& d1,
                                          uint32_t a0, uint32_t a1, uint32_t a2, uint32_t a3,
                                          uint32_t b0, uint32_t b1) {
    asm volatile(
        "mma.sync.aligned.m16n8k16.row.col.f16.f16.f16.f16 "
        "{%0,%1}, {%2,%3,%4,%5}, {%6,%7}, {%0,%1};"
        : "+r"(d0), "+r"(d1)
        : "r"(a0), "r"(a1), "r"(a2), "r"(a3), "r"(b0), "r"(b1));
}

__device__ __forceinline__ void ldsm_x4(uint32_t& r0, uint32_t& r1, uint32_t& r2, uint32_t& r3,
                                        uint32_t saddr) {
    asm volatile("ldmatrix.sync.aligned.m8n8.x4.shared.b16 {%0,%1,%2,%3}, [%4];"
                 : "=r"(r0), "=r"(r1), "=r"(r2), "=r"(r3) : "r"(saddr));
}

#define MBAR_WAIT(m, ph) do {                                                  \
    uint32_t _done;                                                            \
    asm volatile("{\n\t.reg .pred p;\n\t"                                      \
        "mbarrier.try_wait.parity.acquire.cta.shared::cta.b64 p, [%1], %2;\n\t"\
        "selp.b32 %0, 1, 0, p;\n\t}"                                           \
        : "=r"(_done) : "r"(m), "r"(ph) : "memory");                           \
    if (!_done) {                                                              \
        asm volatile("{\n\t.reg .pred P1;\n\t"                                 \
        "WL_%=:\n\t"                                                           \
        "mbarrier.try_wait.parity.acquire.cta.shared::cta.b64 P1, [%0], %1, 0x989680;\n\t" \
        "@P1 bra.uni WD_%=;\n\t"                                               \
        "bra.uni WL_%=;\n\t"                                                   \
        "WD_%=:\n\t}" :: "r"(m), "r"(ph) : "memory");                          \
    }                                                                          \
} while (0)

__device__ __forceinline__ void decode_tile(int idx, int& rt, int& ct) {
    int rem = idx, r = 0;
    while (rem >= NTILES - r) { rem -= NTILES - r; r++; }
    rt = r; ct = r + rem;
}

// full 32KB tile copy (A)
__device__ __forceinline__ void issue_copy(uint32_t dst, uint32_t mbar, int tile) {
    asm volatile("mbarrier.arrive.expect_tx.shared.b64 _, [%0], %1;"
                 :: "r"(mbar), "r"((uint32_t)TILE_BYTES) : "memory");
    const char* src = reinterpret_cast<const char*>(g_zh) + (size_t)tile * TILE_BYTES;
    asm volatile("cp.async.bulk.shared::cta.global.mbarrier::complete_tx::bytes "
                 "[%0], [%1], %2, [%3];"
                 :: "r"(dst), "l"(src), "r"((uint32_t)TILE_BYTES), "r"(mbar) : "memory");
}

// 16KB slab copy (B streaming)
__device__ __forceinline__ void issue_slab(uint32_t dst, uint32_t mbar, int tile, int slab) {
    asm volatile("mbarrier.arrive.expect_tx.shared.b64 _, [%0], %1;"
                 :: "r"(mbar), "r"((uint32_t)SLAB_BYTES) : "memory");
    const char* src = reinterpret_cast<const char*>(g_zh)
                    + (size_t)tile * TILE_BYTES + (size_t)slab * SLAB_BYTES;
    asm volatile("cp.async.bulk.shared::cta.global.mbarrier::complete_tx::bytes "
                 "[%0], [%1], %2, [%3];"
                 :: "r"(dst), "l"(src), "r"((uint32_t)SLAB_BYTES), "r"(mbar) : "memory");
}

// ---------------------------------------------------------------------------
// K1: normalize, 4 rows per warp (MLP=4); write g_zh tile-local SW128 layout.
__global__ void k_normalize(const float* __restrict__ xi, const float* __restrict__ xj) {
    int wid  = threadIdx.x >> 5;
    int lane = threadIdx.x & 31;
    int row0 = blockIdx.x * 32 + wid * 4;

    float4 v[4];
    float ss[4];
    #pragma unroll
    for (int r = 0; r < 4; r++) {
        int row = row0 + r;
        const float* src = (row < BROWS) ? (xi + row * DDIM) : (xj + (row - BROWS) * DDIM);
        v[r] = *reinterpret_cast<const float4*>(src + lane * 4);
        ss[r] = v[r].x * v[r].x + v[r].y * v[r].y + v[r].z * v[r].z + v[r].w * v[r].w;
    }
    #pragma unroll
    for (int o = 16; o > 0; o >>= 1) {
        #pragma unroll
        for (int r = 0; r < 4; r++)
            ss[r] += __shfl_xor_sync(0xffffffffu, ss[r], o);
    }
    #pragma unroll
    for (int r = 0; r < 4; r++) {
        int row = row0 + r;
        float inv = 1.0f / fmaxf(sqrtf(ss[r]), 1e-12f);
        float4 z;
        z.x = v[r].x * inv; z.y = v[r].y * inv; z.z = v[r].z * inv; z.w = v[r].w * inv;
        *reinterpret_cast<float4*>(g_zf + row * DDIM + lane * 4) = z;
        __half2 h0 = __floats2half2_rn(z.x, z.y);
        __half2 h1 = __floats2half2_rn(z.z, z.w);
        uint2 pk = make_uint2(*reinterpret_cast<uint32_t*>(&h0),
                              *reinterpret_cast<uint32_t*>(&h1));
        char* dst = reinterpret_cast<char*>(g_zh)
                  + (row >> 7) * TILE_BYTES + (lane >> 4) * SLAB_BYTES;
        uint32_t wb = (uint32_t)((row & 127) * 128 + (lane & 15) * 8);
        wb ^= (wb >> 3) & 0x70;                   // SW128 swizzle
        *reinterpret_cast<uint2*>(dst + wb) = pk;
    }
}

// ---------------------------------------------------------------------------
// K2: persistent triangular fused GEMM + exp + row/col sums.
// 8 warps = 4(m) x 2(n), warp tile 32x64, software-pipelined ldmatrix.
// A cached per chunk; B streamed per-slab (copy overlaps opposite half).
__global__ __launch_bounds__(256, 3) void k_gemm_exp(void) {
    extern __shared__ char dsm[];
    __shared__ __align__(8) uint64_t s_mbars[3];
    __shared__ float srow[2][128];
    __shared__ float scol[4][128];

    const int tid  = threadIdx.x;
    const int lane = tid & 31;
    const int wid  = tid >> 5;
    const int g    = lane >> 2;
    const int q    = lane & 3;
    const int wr   = wid & 3;        // warp m-row 0..3
    const int wc   = wid >> 2;       // warp n-col 0..1

    const uint32_t dbase = (uint32_t)__cvta_generic_to_shared(dsm);
    const uint32_t abase = (dbase + 1023u) & ~1023u;     // A: 32KB
    const uint32_t bbase = abase + TILE_BYTES;           // B: slab0 @+0, slab1 @+16K
    const uint32_t mbarA  = (uint32_t)__cvta_generic_to_shared(&s_mbars[0]);
    const uint32_t mbarB0 = mbarA + 8;                   // slab0
    const uint32_t mbarB1 = mbarA + 16;                  // slab1

    // ldmatrix lane geometry
    const int sub = lane >> 3;
    const int li  = lane & 7;
    const int aRow0 = wr * 32 + li + ((sub & 1) << 3);
    const int aK16  = (sub >> 1) << 4;
    const int xA    = (aRow0 & 7) << 4;
    const int bRow0 = wc * 64 + li + ((sub >> 1) << 3);
    const int bK16  = (sub & 1) << 4;
    const int xB    = (bRow0 & 7) << 4;

#define A_AD(ks)     (abase + (uint32_t)(((ks) >> 2) * SLAB_BYTES) + (uint32_t)aRow0 * 128 \
                      + (uint32_t)((((ks) & 3) * 32 + aK16) ^ xA))
#define A_AD2(ks)    (abase + (uint32_t)(((ks) >> 2) * SLAB_BYTES) + (uint32_t)(aRow0 + 16) * 128 \
                      + (uint32_t)((((ks) & 3) * 32 + aK16) ^ xA))
#define B_AD(ks, p)  (bbase + (uint32_t)(((ks) >> 2) * SLAB_BYTES) + (uint32_t)(bRow0 + (p) * 16) * 128 \
                      + (uint32_t)((((ks) & 3) * 32 + bK16) ^ xB))

    // chunk assignment: first 304 CTAs take 5 tiles, rest 4 (304*5+140*4=2080)
    const int bid   = blockIdx.x;
    const int start = bid * 4 + min(bid, 304);
    const int count = 4 + (bid < 304 ? 1 : 0);

    if (tid == 0) {
        asm volatile("mbarrier.init.shared.b64 [%0], %1;" :: "r"(mbarA),  "r"(1u) : "memory");
        asm volatile("mbarrier.init.shared.b64 [%0], %1;" :: "r"(mbarB0), "r"(1u) : "memory");
        asm volatile("mbarrier.init.shared.b64 [%0], %1;" :: "r"(mbarB1), "r"(1u) : "memory");
    }
    __syncthreads();

    int rt0, ct0; decode_tile(start, rt0, ct0);
    if (tid == 0) {
        issue_copy(abase, mbarA, rt0);
        issue_slab(bbase,              mbarB0, ct0, 0);
        issue_slab(bbase + SLAB_BYTES, mbarB1, ct0, 1);
    }
    int rtPrev = rt0;
    uint32_t phA = 0, phB0 = 0, phB1 = 0;
    bool aPend = true;

    for (int i = 0; i < count; i++) {
        const int idx = start + i;
        int rt, ct; decode_tile(idx, rt, ct);
        const bool diag = (rt == ct);
        const bool hasNext = (i + 1 < count);
        int rtn = 0, ctn = 0;
        if (hasNext) decode_tile(idx + 1, rtn, ctn);

        if (i > 0 && rt != rtPrev) {      // rare A reload (prev reads done)
            if (tid == 0) issue_copy(abase, mbarA, rt);
            aPend = true;
            rtPrev = rt;
        }

        MBAR_WAIT(mbarB0, phB0); phB0 ^= 1;          // slab0 ready
        if (aPend) { MBAR_WAIT(mbarA, phA); phA ^= 1; aPend = false; }

        uint32_t c[2][8][2];              // f16x2 accumulators
        #pragma unroll
        for (int mi = 0; mi < 2; mi++)
            #pragma unroll
            for (int ni = 0; ni < 8; ni++) {
                c[mi][ni][0] = 0u;
                c[mi][ni][1] = 0u;
            }

        // -------- software-pipelined mainloop (slab-phased) --------
        uint32_t a[2][2][4];
        uint32_t bq[4], bn[4];
        ldsm_x4(a[0][0][0], a[0][0][1], a[0][0][2], a[0][0][3], A_AD(0));
        ldsm_x4(a[0][1][0], a[0][1][1], a[0][1][2], a[0][1][3], A_AD2(0));
        ldsm_x4(bq[0], bq[1], bq[2], bq[3], B_AD(0, 0));

        #pragma unroll
        for (int ks = 0; ks < 8; ks++) {
            if (ks == 3) {                // slab1 first read is ks3,p3 prefetch
                MBAR_WAIT(mbarB1, phB1); phB1 ^= 1;
            }
            if (ks == 4) {                // all slab0 reads issued -> recycle it
                __syncthreads();
                if (tid == 0 && hasNext)
                    issue_slab(bbase, mbarB0, ctn, 0);   // overlaps ks4-7+epilogue
            }
            const int cur = ks & 1, nxt = cur ^ 1;
            #pragma unroll
            for (int p = 0; p < 4; p++) {
                if (p < 3) {
                    ldsm_x4(bn[0], bn[1], bn[2], bn[3], B_AD(ks, p + 1));
                } else if (ks < 7) {
                    ldsm_x4(a[nxt][0][0], a[nxt][0][1], a[nxt][0][2], a[nxt][0][3], A_AD(ks + 1));
                    ldsm_x4(a[nxt][1][0], a[nxt][1][1], a[nxt][1][2], a[nxt][1][3], A_AD2(ks + 1));
                    ldsm_x4(bn[0], bn[1], bn[2], bn[3], B_AD(ks + 1, 0));
                }
                #pragma unroll
                for (int mi = 0; mi < 2; mi++) {
                    mma16816h(c[mi][2*p][0],   c[mi][2*p][1],
                              a[cur][mi][0], a[cur][mi][1], a[cur][mi][2], a[cur][mi][3],
                              bq[0], bq[1]);
                    mma16816h(c[mi][2*p+1][0], c[mi][2*p+1][1],
                              a[cur][mi][0], a[cur][mi][1], a[cur][mi][2], a[cur][mi][3],
                              bq[2], bq[3]);
                }
                bq[0] = bn[0]; bq[1] = bn[1]; bq[2] = bn[2]; bq[3] = bn[3];
            }
        }

        __syncthreads();                  // all slab1 / A reads done
        if (tid == 0 && hasNext)
            issue_slab(bbase + SLAB_BYTES, mbarB1, ctn, 1);  // overlaps epilogue

        // ---- epilogue: unpack f16 pairs -> f32 ex2, diag mask, sums ----
        float rs[2][2];
        rs[0][0] = rs[0][1] = rs[1][0] = rs[1][1] = 0.0f;
        float cs[16];
        #pragma unroll
        for (int v = 0; v < 16; v++) cs[v] = 0.0f;

        #pragma unroll
        for (int ni = 0; ni < 8; ni++) {
            const int lc = wc * 64 + ni * 8 + 2 * q;
            #pragma unroll
            for (int mi = 0; mi < 2; mi++) {
                const int lr0 = wr * 32 + mi * 16 + g;
                const int lr1 = lr0 + 8;
                float2 f01 = __half22float2(*reinterpret_cast<__half2*>(&c[mi][ni][0]));
                float2 f23 = __half22float2(*reinterpret_cast<__half2*>(&c[mi][ni][1]));
                float v0 = ex2f(f01.x * EXP_SCALE);
                float v1 = ex2f(f01.y * EXP_SCALE);
                float v2 = ex2f(f23.x * EXP_SCALE);
                float v3 = ex2f(f23.y * EXP_SCALE);
                if (diag) {
                    if (lr0 == lc)     v0 = 0.0f;
                    if (lr0 == lc + 1) v1 = 0.0f;
                    if (lr1 == lc)     v2 = 0.0f;
                    if (lr1 == lc + 1) v3 = 0.0f;
                }
                rs[mi][0] += v0 + v1;
                rs[mi][1] += v2 + v3;
                cs[2 * ni]     += v0 + v2;
                cs[2 * ni + 1] += v1 + v3;
            }
        }

        if (!diag) {
            #pragma unroll
            for (int i2 = 0; i2 < 8; i2++) {
                float keep = (lane & 4) ? cs[i2 + 8] : cs[i2];
                float give = (lane & 4) ? cs[i2] : cs[i2 + 8];
                cs[i2] = keep + __shfl_xor_sync(0xffffffffu, give, 4);
            }
            #pragma unroll
            for (int i2 = 0; i2 < 4; i2++) {
                float keep = (lane & 8) ? cs[i2 + 4] : cs[i2];
                float give = (lane & 8) ? cs[i2] : cs[i2 + 4];
                cs[i2] = keep + __shfl_xor_sync(0xffffffffu, give, 8);
            }
            #pragma unroll
            for (int i2 = 0; i2 < 2; i2++) {
                float keep = (lane & 16) ? cs[i2 + 2] : cs[i2];
                float give = (lane & 16) ? cs[i2] : cs[i2 + 2];
                cs[i2] = keep + __shfl_xor_sync(0xffffffffu, give, 16);
            }
            const int v0i = ((lane & 4) ? 8 : 0) + ((lane & 8) ? 4 : 0) + ((lane & 16) ? 2 : 0);
            const int col0 = wc * 64 + (v0i >> 1) * 8 + 2 * q;
            scol[wr][col0]     = cs[0];
            scol[wr][col0 + 1] = cs[1];
        }

        #pragma unroll
        for (int mi = 0; mi < 2; mi++) {
            rs[mi][0] += __shfl_xor_sync(0xffffffffu, rs[mi][0], 1);
            rs[mi][0] += __shfl_xor_sync(0xffffffffu, rs[mi][0], 2);
            rs[mi][1] += __shfl_xor_sync(0xffffffffu, rs[mi][1], 1);
            rs[mi][1] += __shfl_xor_sync(0xffffffffu, rs[mi][1], 2);
        }
        if (q == 0) {
            #pragma unroll
            for (int mi = 0; mi < 2; mi++) {
                const int lr = wr * 32 + mi * 16 + g;
                srow[wc][lr]     = rs[mi][0];
                srow[wc][lr + 8] = rs[mi][1];
            }
        }
        __syncthreads();

        if (tid < 128) {
            float v = srow[0][tid] + srow[1][tid];
            g_partial[(rt * 128 + tid) * NTILES + ct] = v;
        } else if (!diag) {
            const int cI = tid - 128;
            float v = scol[0][cI] + scol[1][cI] + scol[2][cI] + scol[3][cI];
            g_partial[(ct * 128 + cI) * NTILES + rt] = v;
        }
    }
#undef A_AD
#undef A_AD2
#undef B_AD
}

// ---------------------------------------------------------------------------
// K3: per-row log-sum + positives + last-block finalize. grid 64 x 128.
__global__ void k_reduce(float* __restrict__ out) {
    int tid  = threadIdx.x;
    int lane = tid & 31, wid = tid >> 5;
    __shared__ float sred1[4], sred2[4];

    int row = blockIdx.x * 128 + tid;
    const float4* p = reinterpret_cast<const float4*>(g_partial + row * NTILES);
    float s = 0.0f;
    #pragma unroll
    for (int i = 0; i < 16; i++) {
        float4 v = p[i];
        s += (v.x + v.y) + (v.z + v.w);
    }
    float lg = logf(s);
    #pragma unroll
    for (int o = 16; o > 0; o >>= 1) lg += __shfl_xor_sync(0xffffffffu, lg, o);
    if (lane == 0) sred1[wid] = lg;

    int pr = blockIdx.x * 64 + (tid >> 1);
    int h  = tid & 1;
    const float4* pa = reinterpret_cast<const float4*>(g_zf + pr * DDIM + h * 64);
    const float4* pb = reinterpret_cast<const float4*>(g_zf + (pr + BROWS) * DDIM + h * 64);
    float d = 0.0f;
    #pragma unroll
    for (int e = 0; e < 16; e++) {
        float4 va = pa[e], vb = pb[e];
        d += va.x * vb.x + va.y * vb.y + va.z * vb.z + va.w * vb.w;
    }
    d += __shfl_xor_sync(0xffffffffu, d, 1);
    float ps = (h == 0) ? d : 0.0f;
    #pragma unroll
    for (int o = 16; o > 0; o >>= 1) ps += __shfl_xor_sync(0xffffffffu, ps, o);
    if (lane == 0) sred2[wid] = ps;

    __syncthreads();
    if (tid == 0) {
        float t1 = sred1[0] + sred1[1] + sred1[2] + sred1[3];
        float t2 = sred2[0] + sred2[1] + sred2[2] + sred2[3];
        g_ploss[blockIdx.x]  = t1;
        g_possum[blockIdx.x] = t2;
        __threadfence();
        int old = atomicAdd(&g_ctr, 1);
        if (old == 63) {
            g_ctr = 0;                         // reset for next graph replay
            volatile float* pl = g_ploss;
            volatile float* pp = g_possum;
            float acc = 0.0f;
            for (int i = 0; i < 64; i++) acc += pl[i] - 20.0f * pp[i];
            out[0] = acc / (float)TWOB;
        }
    }
}

// ---------------------------------------------------------------------------
extern "C" void kernel_launch(void* const* d_in, const int* in_sizes, int n_in,
                              void* d_out, int out_size) {
    const float* xi = (const float*)d_in[0];
    const float* xj = (const float*)d_in[1];
    float* out = (float*)d_out;

    k_normalize<<<TWOB / 32, 256>>>(xi, xj);

    const int smem_bytes = 2 * TILE_BYTES + 1024;   // 66560 -> 3 CTAs/SM
    cudaFuncSetAttribute(k_gemm_exp, cudaFuncAttributeMaxDynamicSharedMemorySize, smem_bytes);
    k_gemm_exp<<<GRID_GEMM, 256, smem_bytes>>>();

    k_reduce<<<64, 128>>>(out);
}

// round 17
// speedup vs baseline: 1.1031x; 1.1031x over previous
#include <cuda_runtime.h>
#include <cuda_fp16.h>
#include <cstdint>

// ---------------------------------------------------------------------------
// SimCLR (NT-Xent) loss, B=4096, D=128, T=0.1 — symmetric triangular GEMM.
// f16 HMMA, 3 CTAs/SM (R15 config). k_normalize handles positive pairs
// (i, i+B) per warp: writes f16 tiles AND pos[i] directly (no fp32 z array).
// ---------------------------------------------------------------------------

#define BROWS    4096
#define TWOB     8192
#define DDIM     128
#define NTILES   64
#define NBLOCKS  (NTILES * (NTILES + 1) / 2)   // 2080
#define TILE_BYTES 32768
#define SLAB_BYTES 16384
#define GRID_GEMM  444                         // 3 per SM
#define EXP_SCALE 14.4269504089f               // 10 * log2(e)

__device__ __half        g_zh[TWOB * DDIM];    // f16, tile-local SW128 layout
__device__ float         g_pos[BROWS];         // fp32 positive dots
__device__ float         g_partial[TWOB * NTILES];  // [row][tile]
__device__ float         g_ploss[64];
__device__ float         g_possum[64];
__device__ int           g_ctr = 0;

// ---------------------------------------------------------------------------
__device__ __forceinline__ float ex2f(float x) {
    float y;
    asm("ex2.approx.ftz.f32 %0, %1;" : "=f"(y) : "f"(x));
    return y;
}

__device__ __forceinline__ void mma16816h(uint32_t& d0, uint32_t& d1,
                                          uint32_t a0, uint32_t a1, uint32_t a2, uint32_t a3,
                                          uint32_t b0, uint32_t b1) {
    asm volatile(
        "mma.sync.aligned.m16n8k16.row.col.f16.f16.f16.f16 "
        "{%0,%1}, {%2,%3,%4,%5}, {%6,%7}, {%0,%1};"
        : "+r"(d0), "+r"(d1)
        : "r"(a0), "r"(a1), "r"(a2), "r"(a3), "r"(b0), "r"(b1));
}

__device__ __forceinline__ void ldsm_x4(uint32_t& r0, uint32_t& r1, uint32_t& r2, uint32_t& r3,
                                        uint32_t saddr) {
    asm volatile("ldmatrix.sync.aligned.m8n8.x4.shared.b16 {%0,%1,%2,%3}, [%4];"
                 : "=r"(r0), "=r"(r1), "=r"(r2), "=r"(r3) : "r"(saddr));
}

#define MBAR_WAIT(m, ph) do {                                                  \
    uint32_t _done;                                                            \
    asm volatile("{\n\t.reg .pred p;\n\t"                                      \
        "mbarrier.try_wait.parity.acquire.cta.shared::cta.b64 p, [%1], %2;\n\t"\
        "selp.b32 %0, 1, 0, p;\n\t}"                                           \
        : "=r"(_done) : "r"(m), "r"(ph) : "memory");                           \
    if (!_done) {                                                              \
        asm volatile("{\n\t.reg .pred P1;\n\t"                                 \
        "WL_%=:\n\t"                                                           \
        "mbarrier.try_wait.parity.acquire.cta.shared::cta.b64 P1, [%0], %1, 0x989680;\n\t" \
        "@P1 bra.uni WD_%=;\n\t"                                               \
        "bra.uni WL_%=;\n\t"                                                   \
        "WD_%=:\n\t}" :: "r"(m), "r"(ph) : "memory");                          \
    }                                                                          \
} while (0)

__device__ __forceinline__ void decode_tile(int idx, int& rt, int& ct) {
    int rem = idx, r = 0;
    while (rem >= NTILES - r) { rem -= NTILES - r; r++; }
    rt = r; ct = r + rem;
}

__device__ __forceinline__ void issue_copy(uint32_t dst, uint32_t mbar, int tile) {
    asm volatile("mbarrier.arrive.expect_tx.shared.b64 _, [%0], %1;"
                 :: "r"(mbar), "r"((uint32_t)TILE_BYTES) : "memory");
    const char* src = reinterpret_cast<const char*>(g_zh) + (size_t)tile * TILE_BYTES;
    asm volatile("cp.async.bulk.shared::cta.global.mbarrier::complete_tx::bytes "
                 "[%0], [%1], %2, [%3];"
                 :: "r"(dst), "l"(src), "r"((uint32_t)TILE_BYTES), "r"(mbar) : "memory");
}

// ---------------------------------------------------------------------------
// K1: normalize; one warp per positive pair (row i and row i+B).
// Writes g_zh (f16 SW128 tiles) and g_pos[i] (fp32) — no fp32 z array.
__global__ void k_normalize(const float* __restrict__ xi, const float* __restrict__ xj) {
    int wid  = threadIdx.x >> 5;
    int lane = threadIdx.x & 31;
    int i    = blockIdx.x * 8 + wid;          // pair index 0..4095

    float4 vA = *reinterpret_cast<const float4*>(xi + i * DDIM + lane * 4);
    float4 vB = *reinterpret_cast<const float4*>(xj + i * DDIM + lane * 4);
    float ssA = vA.x * vA.x + vA.y * vA.y + vA.z * vA.z + vA.w * vA.w;
    float ssB = vB.x * vB.x + vB.y * vB.y + vB.z * vB.z + vB.w * vB.w;
    float dAB = vA.x * vB.x + vA.y * vB.y + vA.z * vB.z + vA.w * vB.w;
    #pragma unroll
    for (int o = 16; o > 0; o >>= 1) {
        ssA += __shfl_xor_sync(0xffffffffu, ssA, o);
        ssB += __shfl_xor_sync(0xffffffffu, ssB, o);
        dAB += __shfl_xor_sync(0xffffffffu, dAB, o);
    }
    float invA = 1.0f / fmaxf(sqrtf(ssA), 1e-12f);
    float invB = 1.0f / fmaxf(sqrtf(ssB), 1e-12f);
    if (lane == 0) g_pos[i] = dAB * invA * invB;

    #pragma unroll
    for (int rr = 0; rr < 2; rr++) {
        int row = rr ? (i + BROWS) : i;
        float4 v = rr ? vB : vA;
        float inv = rr ? invB : invA;
        __half2 h0 = __floats2half2_rn(v.x * inv, v.y * inv);
        __half2 h1 = __floats2half2_rn(v.z * inv, v.w * inv);
        uint2 pk = make_uint2(*reinterpret_cast<uint32_t*>(&h0),
                              *reinterpret_cast<uint32_t*>(&h1));
        char* dst = reinterpret_cast<char*>(g_zh)
                  + (row >> 7) * TILE_BYTES + (lane >> 4) * SLAB_BYTES;
        uint32_t wb = (uint32_t)((row & 127) * 128 + (lane & 15) * 8);
        wb ^= (wb >> 3) & 0x70;                   // SW128 swizzle
        *reinterpret_cast<uint2*>(dst + wb) = pk;
    }
}

// ---------------------------------------------------------------------------
// K2: persistent triangular fused GEMM + exp + row/col sums (R15 config).
// 8 warps = 4(m) x 2(n), warp tile 32x64, software-pipelined ldmatrix.
// A cached per chunk; B single-buffered (next copy issued post-mainloop-sync).
__global__ __launch_bounds__(256, 3) void k_gemm_exp(void) {
    extern __shared__ char dsm[];
    __shared__ __align__(8) uint64_t s_mbars[2];
    __shared__ float srow[2][128];
    __shared__ float scol[4][128];

    const int tid  = threadIdx.x;
    const int lane = tid & 31;
    const int wid  = tid >> 5;
    const int g    = lane >> 2;
    const int q    = lane & 3;
    const int wr   = wid & 3;        // warp m-row 0..3
    const int wc   = wid >> 2;       // warp n-col 0..1

    const uint32_t dbase = (uint32_t)__cvta_generic_to_shared(dsm);
    const uint32_t abase = (dbase + 1023u) & ~1023u;     // A: 32KB
    const uint32_t bbase = abase + TILE_BYTES;           // B: 32KB (single)
    const uint32_t mbarA = (uint32_t)__cvta_generic_to_shared(&s_mbars[0]);
    const uint32_t mbarB = mbarA + 8;

    // ldmatrix lane geometry
    const int sub = lane >> 3;
    const int li  = lane & 7;
    const int aRow0 = wr * 32 + li + ((sub & 1) << 3);
    const int aK16  = (sub >> 1) << 4;
    const int xA    = (aRow0 & 7) << 4;
    const int bRow0 = wc * 64 + li + ((sub >> 1) << 3);
    const int bK16  = (sub & 1) << 4;
    const int xB    = (bRow0 & 7) << 4;

#define A_AD(ks)     (abase + (uint32_t)(((ks) >> 2) * SLAB_BYTES) + (uint32_t)aRow0 * 128 \
                      + (uint32_t)((((ks) & 3) * 32 + aK16) ^ xA))
#define A_AD2(ks)    (abase + (uint32_t)(((ks) >> 2) * SLAB_BYTES) + (uint32_t)(aRow0 + 16) * 128 \
                      + (uint32_t)((((ks) & 3) * 32 + aK16) ^ xA))
#define B_AD(ks, p)  (bbase + (uint32_t)(((ks) >> 2) * SLAB_BYTES) + (uint32_t)(bRow0 + (p) * 16) * 128 \
                      + (uint32_t)((((ks) & 3) * 32 + bK16) ^ xB))

    // chunk assignment: first 304 CTAs take 5 tiles, rest 4 (304*5+140*4=2080)
    const int bid   = blockIdx.x;
    const int start = bid * 4 + min(bid, 304);
    const int count = 4 + (bid < 304 ? 1 : 0);

    if (tid == 0) {
        asm volatile("mbarrier.init.shared.b64 [%0], %1;" :: "r"(mbarA), "r"(1u) : "memory");
        asm volatile("mbarrier.init.shared.b64 [%0], %1;" :: "r"(mbarB), "r"(1u) : "memory");
    }
    __syncthreads();

    int rt0, ct0; decode_tile(start, rt0, ct0);
    if (tid == 0) {
        issue_copy(abase, mbarA, rt0);
        issue_copy(bbase, mbarB, ct0);
    }
    int rtPrev = rt0;
    uint32_t phA = 0, phB = 0;
    bool aPend = true;

    for (int i = 0; i < count; i++) {
        const int idx = start + i;
        int rt, ct; decode_tile(idx, rt, ct);
        const bool diag = (rt == ct);

        if (i > 0 && rt != rtPrev) {      // rare A reload (prev reads done)
            if (tid == 0) issue_copy(abase, mbarA, rt);
            aPend = true;
            rtPrev = rt;
        }

        MBAR_WAIT(mbarB, phB); phB ^= 1;
        if (aPend) { MBAR_WAIT(mbarA, phA); phA ^= 1; aPend = false; }

        uint32_t c[2][8][2];              // f16x2 accumulators
        #pragma unroll
        for (int mi = 0; mi < 2; mi++)
            #pragma unroll
            for (int ni = 0; ni < 8; ni++) {
                c[mi][ni][0] = 0u;
                c[mi][ni][1] = 0u;
            }

        // -------- software-pipelined mainloop --------
        uint32_t a[2][2][4];
        uint32_t bq[4], bn[4];
        ldsm_x4(a[0][0][0], a[0][0][1], a[0][0][2], a[0][0][3], A_AD(0));
        ldsm_x4(a[0][1][0], a[0][1][1], a[0][1][2], a[0][1][3], A_AD2(0));
        ldsm_x4(bq[0], bq[1], bq[2], bq[3], B_AD(0, 0));

        #pragma unroll
        for (int ks = 0; ks < 8; ks++) {
            const int cur = ks & 1, nxt = cur ^ 1;
            #pragma unroll
            for (int p = 0; p < 4; p++) {
                if (p < 3) {
                    ldsm_x4(bn[0], bn[1], bn[2], bn[3], B_AD(ks, p + 1));
                } else if (ks < 7) {
                    ldsm_x4(a[nxt][0][0], a[nxt][0][1], a[nxt][0][2], a[nxt][0][3], A_AD(ks + 1));
                    ldsm_x4(a[nxt][1][0], a[nxt][1][1], a[nxt][1][2], a[nxt][1][3], A_AD2(ks + 1));
                    ldsm_x4(bn[0], bn[1], bn[2], bn[3], B_AD(ks + 1, 0));
                }
                #pragma unroll
                for (int mi = 0; mi < 2; mi++) {
                    mma16816h(c[mi][2*p][0],   c[mi][2*p][1],
                              a[cur][mi][0], a[cur][mi][1], a[cur][mi][2], a[cur][mi][3],
                              bq[0], bq[1]);
                    mma16816h(c[mi][2*p+1][0], c[mi][2*p+1][1],
                              a[cur][mi][0], a[cur][mi][1], a[cur][mi][2], a[cur][mi][3],
                              bq[2], bq[3]);
                }
                bq[0] = bn[0]; bq[1] = bn[1]; bq[2] = bn[2]; bq[3] = bn[3];
            }
        }

        __syncthreads();                  // all warps done reading A/B smem
        if (tid == 0 && i + 1 < count) {  // stream next B (overlaps epilogue)
            int rtn, ctn; decode_tile(idx + 1, rtn, ctn);
            issue_copy(bbase, mbarB, ctn);
        }

        // ---- epilogue: unpack f16 pairs -> f32 ex2, diag mask, sums ----
        float rs[2][2];
        rs[0][0] = rs[0][1] = rs[1][0] = rs[1][1] = 0.0f;
        float cs[16];
        #pragma unroll
        for (int v = 0; v < 16; v++) cs[v] = 0.0f;

        #pragma unroll
        for (int ni = 0; ni < 8; ni++) {
            const int lc = wc * 64 + ni * 8 + 2 * q;
            #pragma unroll
            for (int mi = 0; mi < 2; mi++) {
                const int lr0 = wr * 32 + mi * 16 + g;
                const int lr1 = lr0 + 8;
                float2 f01 = __half22float2(*reinterpret_cast<__half2*>(&c[mi][ni][0]));
                float2 f23 = __half22float2(*reinterpret_cast<__half2*>(&c[mi][ni][1]));
                float v0 = ex2f(f01.x * EXP_SCALE);
                float v1 = ex2f(f01.y * EXP_SCALE);
                float v2 = ex2f(f23.x * EXP_SCALE);
                float v3 = ex2f(f23.y * EXP_SCALE);
                if (diag) {
                    if (lr0 == lc)     v0 = 0.0f;
                    if (lr0 == lc + 1) v1 = 0.0f;
                    if (lr1 == lc)     v2 = 0.0f;
                    if (lr1 == lc + 1) v3 = 0.0f;
                }
                rs[mi][0] += v0 + v1;
                rs[mi][1] += v2 + v3;
                cs[2 * ni]     += v0 + v2;
                cs[2 * ni + 1] += v1 + v3;
            }
        }

        if (!diag) {
            #pragma unroll
            for (int i2 = 0; i2 < 8; i2++) {
                float keep = (lane & 4) ? cs[i2 + 8] : cs[i2];
                float give = (lane & 4) ? cs[i2] : cs[i2 + 8];
                cs[i2] = keep + __shfl_xor_sync(0xffffffffu, give, 4);
            }
            #pragma unroll
            for (int i2 = 0; i2 < 4; i2++) {
                float keep = (lane & 8) ? cs[i2 + 4] : cs[i2];
                float give = (lane & 8) ? cs[i2] : cs[i2 + 4];
                cs[i2] = keep + __shfl_xor_sync(0xffffffffu, give, 8);
            }
            #pragma unroll
            for (int i2 = 0; i2 < 2; i2++) {
                float keep = (lane & 16) ? cs[i2 + 2] : cs[i2];
                float give = (lane & 16) ? cs[i2] : cs[i2 + 2];
                cs[i2] = keep + __shfl_xor_sync(0xffffffffu, give, 16);
            }
            const int v0i = ((lane & 4) ? 8 : 0) + ((lane & 8) ? 4 : 0) + ((lane & 16) ? 2 : 0);
            const int col0 = wc * 64 + (v0i >> 1) * 8 + 2 * q;
            scol[wr][col0]     = cs[0];
            scol[wr][col0 + 1] = cs[1];
        }

        #pragma unroll
        for (int mi = 0; mi < 2; mi++) {
            rs[mi][0] += __shfl_xor_sync(0xffffffffu, rs[mi][0], 1);
            rs[mi][0] += __shfl_xor_sync(0xffffffffu, rs[mi][0], 2);
            rs[mi][1] += __shfl_xor_sync(0xffffffffu, rs[mi][1], 1);
            rs[mi][1] += __shfl_xor_sync(0xffffffffu, rs[mi][1], 2);
        }
        if (q == 0) {
            #pragma unroll
            for (int mi = 0; mi < 2; mi++) {
                const int lr = wr * 32 + mi * 16 + g;
                srow[wc][lr]     = rs[mi][0];
                srow[wc][lr + 8] = rs[mi][1];
            }
        }
        __syncthreads();

        if (tid < 128) {
            float v = srow[0][tid] + srow[1][tid];
            g_partial[(rt * 128 + tid) * NTILES + ct] = v;
        } else if (!diag) {
            const int cI = tid - 128;
            float v = scol[0][cI] + scol[1][cI] + scol[2][cI] + scol[3][cI];
            g_partial[(ct * 128 + cI) * NTILES + rt] = v;
        }
    }
#undef A_AD
#undef A_AD2
#undef B_AD
}

// ---------------------------------------------------------------------------
// K3: per-row log-sum + positive partial sums + last-block finalize.
// grid 64 x 128.
__global__ void k_reduce(float* __restrict__ out) {
    int tid  = threadIdx.x;
    int lane = tid & 31, wid = tid >> 5;
    __shared__ float sred1[4], sred2[4];

    int row = blockIdx.x * 128 + tid;
    const float4* p = reinterpret_cast<const float4*>(g_partial + row * NTILES);
    float s = 0.0f;
    #pragma unroll
    for (int i = 0; i < 16; i++) {
        float4 v = p[i];
        s += (v.x + v.y) + (v.z + v.w);
    }
    float lg = logf(s);
    #pragma unroll
    for (int o = 16; o > 0; o >>= 1) lg += __shfl_xor_sync(0xffffffffu, lg, o);
    if (lane == 0) sred1[wid] = lg;

    // positives: 64 pre-computed values per block
    float ps = (tid < 64) ? g_pos[blockIdx.x * 64 + tid] : 0.0f;
    #pragma unroll
    for (int o = 16; o > 0; o >>= 1) ps += __shfl_xor_sync(0xffffffffu, ps, o);
    if (lane == 0) sred2[wid] = ps;

    __syncthreads();
    if (tid == 0) {
        float t1 = sred1[0] + sred1[1] + sred1[2] + sred1[3];
        float t2 = sred2[0] + sred2[1] + sred2[2] + sred2[3];
        g_ploss[blockIdx.x]  = t1;
        g_possum[blockIdx.x] = t2;
        __threadfence();
        int old = atomicAdd(&g_ctr, 1);
        if (old == 63) {
            g_ctr = 0;                         // reset for next graph replay
            volatile float* pl = g_ploss;
            volatile float* pp = g_possum;
            float acc = 0.0f;
            for (int i = 0; i < 64; i++) acc += pl[i] - 20.0f * pp[i];
            out[0] = acc / (float)TWOB;
        }
    }
}

// ---------------------------------------------------------------------------
extern "C" void kernel_launch(void* const* d_in, const int* in_sizes, int n_in,
                              void* d_out, int out_size) {
    const float* xi = (const float*)d_in[0];
    const float* xj = (const float*)d_in[1];
    float* out = (float*)d_out;

    k_normalize<<<BROWS / 8, 256>>>(xi, xj);

    const int smem_bytes = 2 * TILE_BYTES + 1024;   // 66560 -> 3 CTAs/SM
    cudaFuncSetAttribute(k_gemm_exp, cudaFuncAttributeMaxDynamicSharedMemorySize, smem_bytes);
    k_gemm_exp<<<GRID_GEMM, 256, smem_bytes>>>();

    k_reduce<<<64, 128>>>(out);
}